// round 4
// baseline (speedup 1.0000x reference)
#include <cuda_runtime.h>
#include <cuda_fp16.h>
#include <cstdint>

// Problem constants (fixed shapes for this dataset)
#define BB   4
#define NN   50000
#define CIN  64
#define EE   800000
#define HALF 32
#define BN   (BB * NN)           // 200000

#define SCAT_BLOCKS 782          // ceil(EE/4 / 256)
#define PROJ_BLOCKS 1563         // ceil(NN / 32)
#define SCANB_BLOCKS 49          // ceil(NN/1024)

// ---------------- scratch (device globals; no allocation allowed) ----------
__device__ __half g_hlin[NN * 128];    // [n][ch][b]  half, 12.8 MB (L2-resident)
__device__ int    g_counts[NN];
__device__ int    g_offsets[NN + 1];
__device__ int    g_cursor[NN];
__device__ int2   g_csr[EE];           // .x = col, .y = bits(val)
__device__ int    g_blocksums[64];
__device__ float  g_wstage[64 * 64];   // staging for transposed W

__constant__ float cW[64][64];         // [c][o]: o 0..31 = Wlin, 32..63 = Weye

// ---------------- f32x2 helpers --------------------------------------------
__device__ __forceinline__ void ffma2(unsigned long long& d,
                                      unsigned long long a,
                                      unsigned long long b) {
    asm("fma.rn.f32x2 %0, %1, %2, %0;" : "+l"(d) : "l"(a), "l"(b));
}
__device__ __forceinline__ unsigned long long dup2(float v) {
    unsigned long long d;
    unsigned u = __float_as_uint(v);
    asm("mov.b64 %0, {%1, %1};" : "=l"(d) : "r"(u));
    return d;
}
__device__ __forceinline__ float lo32(unsigned long long v) {
    return __uint_as_float((unsigned)v);
}
__device__ __forceinline__ float hi32(unsigned long long v) {
    return __uint_as_float((unsigned)(v >> 32));
}

// ---------------- W transpose staging ---------------------------------------
__global__ __launch_bounds__(256) void transpose_w_kernel(
    const float* __restrict__ Wlin, const float* __restrict__ Weye) {
    int idx = blockIdx.x * 256 + threadIdx.x;    // 16 blocks -> 4096
    if (idx < 4096) {
        int o = idx & 63, c = idx >> 6;
        g_wstage[c * 64 + o] = (o < 32) ? Wlin[o * 64 + c]
                                        : Weye[(o - 32) * 64 + c];
    }
}

// ---------------- histogram of rows (int4 vectorized) ------------------------
__global__ __launch_bounds__(256) void hist_kernel(const int4* __restrict__ rows4) {
    int i = blockIdx.x * blockDim.x + threadIdx.x;
    if (i < EE / 4) {
        int4 r = rows4[i];
        atomicAdd(&g_counts[r.x], 1);
        atomicAdd(&g_counts[r.y], 1);
        atomicAdd(&g_counts[r.z], 1);
        atomicAdd(&g_counts[r.w], 1);
    }
}

// ---------------- scan phase A: per-1024-chunk sums --------------------------
__global__ __launch_bounds__(1024) void scanA_kernel() {
    __shared__ int ws[32];
    const int tid = threadIdx.x, lane = tid & 31, wid = tid >> 5;
    int i = blockIdx.x * 1024 + tid;
    int v = (i < NN) ? g_counts[i] : 0;
    #pragma unroll
    for (int d = 16; d > 0; d >>= 1) v += __shfl_down_sync(0xFFFFFFFFu, v, d);
    if (lane == 0) ws[wid] = v;
    __syncthreads();
    if (tid < 32) {
        int s = ws[tid];
        #pragma unroll
        for (int d = 16; d > 0; d >>= 1) s += __shfl_down_sync(0xFFFFFFFFu, s, d);
        if (tid == 0) g_blocksums[blockIdx.x] = s;
    }
}

// ---------------- scan phase B: local scan + parallel base -------------------
__global__ __launch_bounds__(1024) void scanB_kernel() {
    __shared__ int wsum[32];
    __shared__ int sbase;
    const int tid = threadIdx.x, lane = tid & 31, wid = tid >> 5;
    const int j = blockIdx.x;

    // parallel base = sum of g_blocksums[0..j-1] (warp 0)
    if (wid == 0) {
        int v = 0;
        for (int k = lane; k < j; k += 32) v += g_blocksums[k];
        #pragma unroll
        for (int d = 16; d > 0; d >>= 1) v += __shfl_down_sync(0xFFFFFFFFu, v, d);
        if (lane == 0) sbase = v;
    }

    int i = j * 1024 + tid;
    int v = (i < NN) ? g_counts[i] : 0;
    int x = v;
    #pragma unroll
    for (int d = 1; d < 32; d <<= 1) {
        int y = __shfl_up_sync(0xFFFFFFFFu, x, d);
        if (lane >= d) x += y;
    }
    if (lane == 31) wsum[wid] = x;
    __syncthreads();
    if (tid < 32) {
        int s = wsum[tid];
        #pragma unroll
        for (int d = 1; d < 32; d <<= 1) {
            int y = __shfl_up_sync(0xFFFFFFFFu, s, d);
            if (tid >= d) s += y;
        }
        wsum[tid] = s;
    }
    __syncthreads();
    int incl = x + (wid ? wsum[wid - 1] : 0) + sbase;
    if (i < NN) {
        int excl = incl - v;
        g_offsets[i] = excl;
        g_cursor[i]  = excl;
    }
    if (j == 0 && tid == 0) g_offsets[NN] = EE;
}

// ---------------- fused: CSR scatter + projection ----------------------------
// proj tile: 32 nodes x 4 batches x 64 outs; 256 threads.
//   node = tid&31, og = tid>>5 (warp-uniform out octet). W from __constant__.
__global__ __launch_bounds__(256, 4) void fused_scatter_proj_kernel(
    const int*   __restrict__ rows,
    const int*   __restrict__ cols,
    const float* __restrict__ vals,
    const float* __restrict__ x,
    const float* __restrict__ beye,
    float*       __restrict__ out)
{
    __shared__ float xs[128][65];   // [b*32+node][c], stride 65 = conflict-free

    const int tid = threadIdx.x;

    if (blockIdx.x < SCAT_BLOCKS) {
        // ---- scatter: 4 edges / thread via int4/float4 ----
        int i = blockIdx.x * 256 + tid;
        if (i < EE / 4) {
            int4   r4 = ((const int4*)rows)[i];
            int4   c4 = ((const int4*)cols)[i];
            float4 v4 = ((const float4*)vals)[i];
            int p;
            p = atomicAdd(&g_cursor[r4.x], 1);
            g_csr[p] = make_int2(c4.x, __float_as_int(v4.x));
            p = atomicAdd(&g_cursor[r4.y], 1);
            g_csr[p] = make_int2(c4.y, __float_as_int(v4.y));
            p = atomicAdd(&g_cursor[r4.z], 1);
            g_csr[p] = make_int2(c4.z, __float_as_int(v4.z));
            p = atomicAdd(&g_cursor[r4.w], 1);
            g_csr[p] = make_int2(c4.w, __float_as_int(v4.w));
        }
        return;
    }

    // ---- projection ----
    const int node0 = (blockIdx.x - SCAT_BLOCKS) * 32;

    // load x tile: 128 rows (4b x 32 nodes) x 64 ch, float4 global loads
    for (int idx = tid; idx < 2048; idx += 256) {
        int row  = idx >> 4;            // 0..127
        int b    = row >> 5;
        int node = row & 31;
        int nn   = node0 + node; if (nn >= NN) nn = NN - 1;   // clamp (reads only)
        int c    = (idx & 15) << 2;
        float4 v = *(const float4*)(x + ((size_t)(b * NN + nn)) * 64 + c);
        xs[row][c] = v.x; xs[row][c + 1] = v.y;
        xs[row][c + 2] = v.z; xs[row][c + 3] = v.w;
    }
    __syncthreads();

    const int node = tid & 31;
    const int og   = tid >> 5;           // 0..7, warp-uniform
    const int n    = node0 + node;
    const bool live = (n < NN);

    unsigned long long acc[4][4];
    #pragma unroll
    for (int b = 0; b < 4; ++b)
        #pragma unroll
        for (int j = 0; j < 4; ++j) acc[b][j] = 0ull;

    #pragma unroll 8
    for (int c = 0; c < 64; ++c) {
        const unsigned long long* wrow =
            (const unsigned long long*)&cW[c][og * 8];
        unsigned long long w0 = wrow[0], w1 = wrow[1], w2 = wrow[2], w3 = wrow[3];
        #pragma unroll
        for (int b = 0; b < 4; ++b) {
            unsigned long long a = dup2(xs[b * 32 + node][c]);
            ffma2(acc[b][0], a, w0);
            ffma2(acc[b][1], a, w1);
            ffma2(acc[b][2], a, w2);
            ffma2(acc[b][3], a, w3);
        }
    }

    if (!live) return;

    if (og < 4) {
        // lin half (outs 0..31) -> g_hlin[n][ch][b] packed halves
        const int och = og * 8;
        #pragma unroll
        for (int j = 0; j < 4; ++j) {
            int ch = och + 2 * j;
            __half2 lo01 = __floats2half2_rn(lo32(acc[0][j]), lo32(acc[1][j]));
            __half2 lo23 = __floats2half2_rn(lo32(acc[2][j]), lo32(acc[3][j]));
            __half2 hi01 = __floats2half2_rn(hi32(acc[0][j]), hi32(acc[1][j]));
            __half2 hi23 = __floats2half2_rn(hi32(acc[2][j]), hi32(acc[3][j]));
            uint2 u0, u1;
            u0.x = *(unsigned*)&lo01; u0.y = *(unsigned*)&lo23;
            u1.x = *(unsigned*)&hi01; u1.y = *(unsigned*)&hi23;
            *(uint2*)&g_hlin[(size_t)n * 128 + ch * 4]       = u0;
            *(uint2*)&g_hlin[(size_t)n * 128 + (ch + 1) * 4] = u1;
        }
    } else {
        // eye half (outs 32..63) + bias -> out
        const int och = og * 8;          // 32..56
        float be[8];
        #pragma unroll
        for (int k = 0; k < 8; ++k) be[k] = __ldg(&beye[och - 32 + k]);
        #pragma unroll
        for (int b = 0; b < 4; ++b) {
            float* dst = &out[((size_t)b * NN + n) * 64 + och];
            float4 v0, v1;
            v0.x = lo32(acc[b][0]) + be[0];
            v0.y = hi32(acc[b][0]) + be[1];
            v0.z = lo32(acc[b][1]) + be[2];
            v0.w = hi32(acc[b][1]) + be[3];
            v1.x = lo32(acc[b][2]) + be[4];
            v1.y = hi32(acc[b][2]) + be[5];
            v1.z = lo32(acc[b][3]) + be[6];
            v1.w = hi32(acc[b][3]) + be[7];
            *(float4*)dst = v0;
            *(float4*)(dst + 4) = v1;
        }
    }
}

// ---------------- gather: one warp per node, all 4 batches, fp16 h ----------
__global__ __launch_bounds__(256) void gather_kernel(const float* __restrict__ blin,
                                                     float* __restrict__ out) {
    int n    = (blockIdx.x * blockDim.x + threadIdx.x) >> 5;
    int lane = threadIdx.x & 31;
    if (n >= NN) return;

    int s = g_offsets[n];
    int t = g_offsets[n + 1];

    float a0 = 0.f, a1 = 0.f, a2 = 0.f, a3 = 0.f;
    int e = s;
    for (; e + 2 <= t; e += 2) {
        int2 p0 = g_csr[e];
        int2 p1 = g_csr[e + 1];
        uint2 q0 = *(const uint2*)(g_hlin + (size_t)p0.x * 128 + lane * 4);
        uint2 q1 = *(const uint2*)(g_hlin + (size_t)p1.x * 128 + lane * 4);
        float s0 = __int_as_float(p0.y);
        float s1 = __int_as_float(p1.y);
        float2 u01 = __half22float2(*(__half2*)&q0.x);
        float2 u23 = __half22float2(*(__half2*)&q0.y);
        float2 v01 = __half22float2(*(__half2*)&q1.x);
        float2 v23 = __half22float2(*(__half2*)&q1.y);
        a0 += s0 * u01.x; a1 += s0 * u01.y; a2 += s0 * u23.x; a3 += s0 * u23.y;
        a0 += s1 * v01.x; a1 += s1 * v01.y; a2 += s1 * v23.x; a3 += s1 * v23.y;
    }
    if (e < t) {
        int2 p = g_csr[e];
        uint2 q = *(const uint2*)(g_hlin + (size_t)p.x * 128 + lane * 4);
        float sv = __int_as_float(p.y);
        float2 u01 = __half22float2(*(__half2*)&q.x);
        float2 u23 = __half22float2(*(__half2*)&q.y);
        a0 += sv * u01.x; a1 += sv * u01.y; a2 += sv * u23.x; a3 += sv * u23.y;
    }

    float bl = blin[lane];
    out[((size_t)0 * NN + n) * 64 + lane] = a0 + bl;
    out[((size_t)1 * NN + n) * 64 + lane] = a1 + bl;
    out[((size_t)2 * NN + n) * 64 + lane] = a2 + bl;
    out[((size_t)3 * NN + n) * 64 + lane] = a3 + bl;
}

// ---------------- launch -----------------------------------------------------
extern "C" void kernel_launch(void* const* d_in, const int* in_sizes, int n_in,
                              void* d_out, int out_size) {
    const float* x    = (const float*)d_in[0];
    const float* vals = (const float*)d_in[1];
    const float* Wlin = (const float*)d_in[2];
    const float* blin = (const float*)d_in[3];
    const float* Weye = (const float*)d_in[4];
    const float* beye = (const float*)d_in[5];
    const int*   rows = (const int*)d_in[6];
    const int*   cols = (const int*)d_in[7];
    float* out = (float*)d_out;
    (void)in_sizes; (void)n_in; (void)out_size;

    // Stage transposed W and copy into constant memory (D2D memcpy node)
    transpose_w_kernel<<<16, 256>>>(Wlin, Weye);
    void* cw_ptr = nullptr;
    void* ws_ptr = nullptr;
    cudaGetSymbolAddress(&cw_ptr, cW);
    cudaGetSymbolAddress(&ws_ptr, g_wstage);
    cudaMemcpyAsync(cw_ptr, ws_ptr, 64 * 64 * sizeof(float),
                    cudaMemcpyDeviceToDevice);

    void* counts_ptr = nullptr;
    cudaGetSymbolAddress(&counts_ptr, g_counts);
    cudaMemsetAsync(counts_ptr, 0, NN * sizeof(int));

    hist_kernel<<<(EE / 4 + 255) / 256, 256>>>((const int4*)rows);
    scanA_kernel<<<SCANB_BLOCKS, 1024>>>();
    scanB_kernel<<<SCANB_BLOCKS, 1024>>>();
    fused_scatter_proj_kernel<<<SCAT_BLOCKS + PROJ_BLOCKS, 256>>>(
        rows, cols, vals, x, beye, out);
    gather_kernel<<<(NN * 32 + 255) / 256, 256>>>(blin, out);
}

// round 6
// speedup vs baseline: 1.1862x; 1.1862x over previous
#include <cuda_runtime.h>
#include <cuda_fp16.h>
#include <cstdint>

// Problem constants (fixed shapes for this dataset)
#define BB   4
#define NN   50000
#define CIN  64
#define EE   800000
#define HALF 32
#define BN   (BB * NN)           // 200000

#define SCAT_BLOCKS 782          // ceil(EE/4 / 256)
#define PROJ_BLOCKS 3125         // BN / 64
#define SCANB_BLOCKS 49          // ceil(NN/1024)

// ---------------- scratch (device globals; no allocation allowed) ----------
__device__ __half g_hlin[NN * 128];    // [n][ch][b]  half, 12.8 MB (L2-resident)
__device__ int    g_counts[NN];
__device__ int    g_offsets[NN + 1];
__device__ int    g_cursor[NN];
__device__ int2   g_csr[EE];           // .x = col, .y = bits(val)
__device__ int    g_blocksums[64];

// ---------------- mma helper -------------------------------------------------
__device__ __forceinline__ void mma16816(float& d0, float& d1, float& d2, float& d3,
                                         unsigned a0, unsigned a1, unsigned a2, unsigned a3,
                                         unsigned b0, unsigned b1) {
    asm("mma.sync.aligned.m16n8k16.row.col.f32.f16.f16.f32 "
        "{%0,%1,%2,%3}, {%4,%5,%6,%7}, {%8,%9}, {%0,%1,%2,%3};"
        : "+f"(d0), "+f"(d1), "+f"(d2), "+f"(d3)
        : "r"(a0), "r"(a1), "r"(a2), "r"(a3), "r"(b0), "r"(b1));
}

// ---------------- histogram of rows (int4 vectorized) ------------------------
__global__ __launch_bounds__(256) void hist_kernel(const int4* __restrict__ rows4) {
    int i = blockIdx.x * blockDim.x + threadIdx.x;
    if (i < EE / 4) {
        int4 r = rows4[i];
        atomicAdd(&g_counts[r.x], 1);
        atomicAdd(&g_counts[r.y], 1);
        atomicAdd(&g_counts[r.z], 1);
        atomicAdd(&g_counts[r.w], 1);
    }
}

// ---------------- scan phase A: per-1024-chunk sums --------------------------
__global__ __launch_bounds__(1024) void scanA_kernel() {
    __shared__ int ws[32];
    const int tid = threadIdx.x, lane = tid & 31, wid = tid >> 5;
    int i = blockIdx.x * 1024 + tid;
    int v = (i < NN) ? g_counts[i] : 0;
    #pragma unroll
    for (int d = 16; d > 0; d >>= 1) v += __shfl_down_sync(0xFFFFFFFFu, v, d);
    if (lane == 0) ws[wid] = v;
    __syncthreads();
    if (tid < 32) {
        int s = ws[tid];
        #pragma unroll
        for (int d = 16; d > 0; d >>= 1) s += __shfl_down_sync(0xFFFFFFFFu, s, d);
        if (tid == 0) g_blocksums[blockIdx.x] = s;
    }
}

// ---------------- scan phase B: local scan + parallel base -------------------
__global__ __launch_bounds__(1024) void scanB_kernel() {
    __shared__ int wsum[32];
    __shared__ int sbase;
    const int tid = threadIdx.x, lane = tid & 31, wid = tid >> 5;
    const int j = blockIdx.x;

    if (wid == 0) {
        int v = 0;
        for (int k = lane; k < j; k += 32) v += g_blocksums[k];
        #pragma unroll
        for (int d = 16; d > 0; d >>= 1) v += __shfl_down_sync(0xFFFFFFFFu, v, d);
        if (lane == 0) sbase = v;
    }

    int i = j * 1024 + tid;
    int v = (i < NN) ? g_counts[i] : 0;
    int x = v;
    #pragma unroll
    for (int d = 1; d < 32; d <<= 1) {
        int y = __shfl_up_sync(0xFFFFFFFFu, x, d);
        if (lane >= d) x += y;
    }
    if (lane == 31) wsum[wid] = x;
    __syncthreads();
    if (tid < 32) {
        int s = wsum[tid];
        #pragma unroll
        for (int d = 1; d < 32; d <<= 1) {
            int y = __shfl_up_sync(0xFFFFFFFFu, s, d);
            if (tid >= d) s += y;
        }
        wsum[tid] = s;
    }
    __syncthreads();
    int incl = x + (wid ? wsum[wid - 1] : 0) + sbase;
    if (i < NN) {
        int excl = incl - v;
        g_offsets[i] = excl;
        g_cursor[i]  = excl;
    }
    if (j == 0 && tid == 0) g_offsets[NN] = EE;
}

// ---------------- fused: CSR scatter + HMMA projection -----------------------
// proj tile: 64 bn-rows x 64 outs, 128 threads (4 warps x 16 rows).
// fp16 mma.sync.m16n8k16, fp32 accumulate.
#define XS_STRIDE 72   // halves; (stride*2 bytes)=144 -> bank = 4g+tig, conflict-free
__global__ __launch_bounds__(128) void fused_scatter_proj_kernel(
    const int*   __restrict__ rows,
    const int*   __restrict__ cols,
    const float* __restrict__ vals,
    const float* __restrict__ x,
    const float* __restrict__ Wlin,
    const float* __restrict__ Weye,
    const float* __restrict__ beye,
    float*       __restrict__ out)
{
    __shared__ __half xs[64 * XS_STRIDE];   // [row][k] fp16 x tile
    __shared__ __half wt[64 * XS_STRIDE];   // [n][k]  fp16 W^T (n 0..31 lin, 32..63 eye)

    const int tid = threadIdx.x;

    if (blockIdx.x < SCAT_BLOCKS) {
        // ---- scatter: 4 edges / thread via int4/float4 ----
        int i = blockIdx.x * 256 + (tid + ((blockIdx.x & 1) << 7));   // 2 blocks/256-chunk? no:
        // NOTE: blocks are 128 threads; pair two quarters per thread instead.
        i = blockIdx.x * 256 + tid;
        #pragma unroll
        for (int k = 0; k < 2; ++k) {
            int ii = i + k * 128;
            if (ii < EE / 4) {
                int4   r4 = ((const int4*)rows)[ii];
                int4   c4 = ((const int4*)cols)[ii];
                float4 v4 = ((const float4*)vals)[ii];
                int p;
                p = atomicAdd(&g_cursor[r4.x], 1);
                g_csr[p] = make_int2(c4.x, __float_as_int(v4.x));
                p = atomicAdd(&g_cursor[r4.y], 1);
                g_csr[p] = make_int2(c4.y, __float_as_int(v4.y));
                p = atomicAdd(&g_cursor[r4.z], 1);
                g_csr[p] = make_int2(c4.z, __float_as_int(v4.z));
                p = atomicAdd(&g_cursor[r4.w], 1);
                g_csr[p] = make_int2(c4.w, __float_as_int(v4.w));
            }
        }
        return;
    }

    // ---- projection ----
    const int node0 = (blockIdx.x - SCAT_BLOCKS) * 64;   // bn row base

    // Stage x tile (64 rows x 64 k) and W^T (64 n x 64 k) as fp16.
    #pragma unroll
    for (int it = 0; it < 8; ++it) {
        int idx = tid + it * 128;          // 0..1023 float4 slots
        int row = idx >> 4;
        int c4  = (idx & 15) << 2;
        // x
        float4 v = *(const float4*)(x + ((size_t)(node0 + row)) * 64 + c4);
        __half2 h01 = __floats2half2_rn(v.x, v.y);
        __half2 h23 = __floats2half2_rn(v.z, v.w);
        *(__half2*)&xs[row * XS_STRIDE + c4]     = h01;
        *(__half2*)&xs[row * XS_STRIDE + c4 + 2] = h23;
        // W
        const float* wsrc = (row < 32) ? (Wlin + row * 64 + c4)
                                       : (Weye + (row - 32) * 64 + c4);
        float4 w = *(const float4*)wsrc;
        __half2 w01 = __floats2half2_rn(w.x, w.y);
        __half2 w23 = __floats2half2_rn(w.z, w.w);
        *(__half2*)&wt[row * XS_STRIDE + c4]     = w01;
        *(__half2*)&wt[row * XS_STRIDE + c4 + 2] = w23;
    }
    __syncthreads();

    const int warp = tid >> 5;
    const int lane = tid & 31;
    const int g    = lane >> 2;        // group 0..7
    const int tig  = lane & 3;         // thread-in-group
    const int wrow = warp * 16;        // warp's row base within tile

    float d[8][4];
    #pragma unroll
    for (int nf = 0; nf < 8; ++nf)
        #pragma unroll
        for (int k = 0; k < 4; ++k) d[nf][k] = 0.f;

    #pragma unroll
    for (int kc = 0; kc < 4; ++kc) {
        const int kb = kc * 16;
        unsigned a0 = *(const unsigned*)&xs[(wrow + g)     * XS_STRIDE + kb + 2 * tig];
        unsigned a1 = *(const unsigned*)&xs[(wrow + g + 8) * XS_STRIDE + kb + 2 * tig];
        unsigned a2 = *(const unsigned*)&xs[(wrow + g)     * XS_STRIDE + kb + 2 * tig + 8];
        unsigned a3 = *(const unsigned*)&xs[(wrow + g + 8) * XS_STRIDE + kb + 2 * tig + 8];
        #pragma unroll
        for (int nf = 0; nf < 8; ++nf) {
            unsigned b0 = *(const unsigned*)&wt[(nf * 8 + g) * XS_STRIDE + kb + 2 * tig];
            unsigned b1 = *(const unsigned*)&wt[(nf * 8 + g) * XS_STRIDE + kb + 2 * tig + 8];
            mma16816(d[nf][0], d[nf][1], d[nf][2], d[nf][3],
                     a0, a1, a2, a3, b0, b1);
        }
    }

    // biases for the 2 eye columns this thread owns per eye frag
    float be[4][2];
    #pragma unroll
    for (int nf = 4; nf < 8; ++nf) {
        int oc = nf * 8 + 2 * tig - 32;
        be[nf - 4][0] = __ldg(&beye[oc]);
        be[nf - 4][1] = __ldg(&beye[oc + 1]);
    }

    // epilogue: two rows per thread (r and r+8)
    #pragma unroll
    for (int half_ = 0; half_ < 2; ++half_) {
        int r  = wrow + g + half_ * 8;
        int bn = node0 + r;
        int b  = bn / NN;
        int n  = bn - b * NN;
        // lin frags -> g_hlin[n][ch][b]
        #pragma unroll
        for (int nf = 0; nf < 4; ++nf) {
            int ch = nf * 8 + 2 * tig;
            float v0 = half_ ? d[nf][2] : d[nf][0];
            float v1 = half_ ? d[nf][3] : d[nf][1];
            g_hlin[(size_t)n * 128 + ch * 4 + b]       = __float2half_rn(v0);
            g_hlin[(size_t)n * 128 + (ch + 1) * 4 + b] = __float2half_rn(v1);
        }
        // eye frags -> out[bn][och..och+1] + bias
        #pragma unroll
        for (int nf = 4; nf < 8; ++nf) {
            int och = nf * 8 + 2 * tig;
            float v0 = (half_ ? d[nf][2] : d[nf][0]) + be[nf - 4][0];
            float v1 = (half_ ? d[nf][3] : d[nf][1]) + be[nf - 4][1];
            *(float2*)&out[(size_t)bn * 64 + och] = make_float2(v0, v1);
        }
    }
}

// ---------------- gather: one warp per node, all 4 batches, fp16 h ----------
__global__ __launch_bounds__(256) void gather_kernel(const float* __restrict__ blin,
                                                     float* __restrict__ out) {
    int n    = (blockIdx.x * blockDim.x + threadIdx.x) >> 5;
    int lane = threadIdx.x & 31;
    if (n >= NN) return;

    int s = g_offsets[n];
    int t = g_offsets[n + 1];

    float a0 = 0.f, a1 = 0.f, a2 = 0.f, a3 = 0.f;
    int e = s;
    for (; e + 2 <= t; e += 2) {
        int2 p0 = g_csr[e];
        int2 p1 = g_csr[e + 1];
        uint2 q0 = *(const uint2*)(g_hlin + (size_t)p0.x * 128 + lane * 4);
        uint2 q1 = *(const uint2*)(g_hlin + (size_t)p1.x * 128 + lane * 4);
        float s0 = __int_as_float(p0.y);
        float s1 = __int_as_float(p1.y);
        float2 u01 = __half22float2(*(__half2*)&q0.x);
        float2 u23 = __half22float2(*(__half2*)&q0.y);
        float2 v01 = __half22float2(*(__half2*)&q1.x);
        float2 v23 = __half22float2(*(__half2*)&q1.y);
        a0 += s0 * u01.x; a1 += s0 * u01.y; a2 += s0 * u23.x; a3 += s0 * u23.y;
        a0 += s1 * v01.x; a1 += s1 * v01.y; a2 += s1 * v23.x; a3 += s1 * v23.y;
    }
    if (e < t) {
        int2 p = g_csr[e];
        uint2 q = *(const uint2*)(g_hlin + (size_t)p.x * 128 + lane * 4);
        float sv = __int_as_float(p.y);
        float2 u01 = __half22float2(*(__half2*)&q.x);
        float2 u23 = __half22float2(*(__half2*)&q.y);
        a0 += sv * u01.x; a1 += sv * u01.y; a2 += sv * u23.x; a3 += sv * u23.y;
    }

    float bl = blin[lane];
    out[((size_t)0 * NN + n) * 64 + lane] = a0 + bl;
    out[((size_t)1 * NN + n) * 64 + lane] = a1 + bl;
    out[((size_t)2 * NN + n) * 64 + lane] = a2 + bl;
    out[((size_t)3 * NN + n) * 64 + lane] = a3 + bl;
}

// ---------------- launch -----------------------------------------------------
extern "C" void kernel_launch(void* const* d_in, const int* in_sizes, int n_in,
                              void* d_out, int out_size) {
    const float* x    = (const float*)d_in[0];
    const float* vals = (const float*)d_in[1];
    const float* Wlin = (const float*)d_in[2];
    const float* blin = (const float*)d_in[3];
    const float* Weye = (const float*)d_in[4];
    const float* beye = (const float*)d_in[5];
    const int*   rows = (const int*)d_in[6];
    const int*   cols = (const int*)d_in[7];
    float* out = (float*)d_out;
    (void)in_sizes; (void)n_in; (void)out_size;

    void* counts_ptr = nullptr;
    cudaGetSymbolAddress(&counts_ptr, g_counts);
    cudaMemsetAsync(counts_ptr, 0, NN * sizeof(int));

    hist_kernel<<<(EE / 4 + 255) / 256, 256>>>((const int4*)rows);
    scanA_kernel<<<SCANB_BLOCKS, 1024>>>();
    scanB_kernel<<<SCANB_BLOCKS, 1024>>>();
    fused_scatter_proj_kernel<<<SCAT_BLOCKS + PROJ_BLOCKS, 128>>>(
        rows, cols, vals, x, Wlin, Weye, beye, out);
    gather_kernel<<<(NN * 32 + 255) / 256, 256>>>(blin, out);
}

// round 7
// speedup vs baseline: 1.8494x; 1.5591x over previous
#include <cuda_runtime.h>
#include <cuda_fp16.h>
#include <cstdint>

// Problem constants (fixed shapes for this dataset)
#define BB   4
#define NN   50000
#define CIN  64
#define EE   800000
#define HALF 32
#define BN   (BB * NN)           // 200000

#define SCAT_BLOCKS 782          // ceil(EE/4 / 256)
#define PROJ_BLOCKS 1563         // ceil(NN / 32)
#define SCANB_BLOCKS 49          // ceil(NN/1024)

// ---------------- scratch (device globals; zero-initialized at load) --------
__device__ __half g_hlin[NN * 128];    // [n][ch][b]  half, 12.8 MB (L2-resident)
__device__ int    g_counts[NN];        // kept zero between calls (scanB re-zeros)
__device__ int    g_offsets[NN + 1];
__device__ int    g_cursor[NN];
__device__ int2   g_csr[EE];           // .x = col, .y = bits(val)
__device__ int    g_blocksums[64];

// ---------------- mma helper -------------------------------------------------
__device__ __forceinline__ void mma16816(float& d0, float& d1, float& d2, float& d3,
                                         unsigned a0, unsigned a1, unsigned a2, unsigned a3,
                                         unsigned b0, unsigned b1) {
    asm("mma.sync.aligned.m16n8k16.row.col.f32.f16.f16.f32 "
        "{%0,%1,%2,%3}, {%4,%5,%6,%7}, {%8,%9}, {%0,%1,%2,%3};"
        : "+f"(d0), "+f"(d1), "+f"(d2), "+f"(d3)
        : "r"(a0), "r"(a1), "r"(a2), "r"(a3), "r"(b0), "r"(b1));
}

// ---------------- scan phase A: per-1024-chunk sums --------------------------
__global__ __launch_bounds__(1024) void scanA_kernel() {
    __shared__ int ws[32];
    const int tid = threadIdx.x, lane = tid & 31, wid = tid >> 5;
    int i = blockIdx.x * 1024 + tid;
    int v = (i < NN) ? g_counts[i] : 0;
    #pragma unroll
    for (int d = 16; d > 0; d >>= 1) v += __shfl_down_sync(0xFFFFFFFFu, v, d);
    if (lane == 0) ws[wid] = v;
    __syncthreads();
    if (tid < 32) {
        int s = ws[tid];
        #pragma unroll
        for (int d = 16; d > 0; d >>= 1) s += __shfl_down_sync(0xFFFFFFFFu, s, d);
        if (tid == 0) g_blocksums[blockIdx.x] = s;
    }
}

// ---------------- scan phase B: local scan + parallel base; re-zero counts ---
__global__ __launch_bounds__(1024) void scanB_kernel() {
    __shared__ int wsum[32];
    __shared__ int sbase;
    const int tid = threadIdx.x, lane = tid & 31, wid = tid >> 5;
    const int j = blockIdx.x;

    if (wid == 0) {
        int v = 0;
        for (int k = lane; k < j; k += 32) v += g_blocksums[k];
        #pragma unroll
        for (int d = 16; d > 0; d >>= 1) v += __shfl_down_sync(0xFFFFFFFFu, v, d);
        if (lane == 0) sbase = v;
    }

    int i = j * 1024 + tid;
    int v = (i < NN) ? g_counts[i] : 0;
    int x = v;
    #pragma unroll
    for (int d = 1; d < 32; d <<= 1) {
        int y = __shfl_up_sync(0xFFFFFFFFu, x, d);
        if (lane >= d) x += y;
    }
    if (lane == 31) wsum[wid] = x;
    __syncthreads();
    if (tid < 32) {
        int s = wsum[tid];
        #pragma unroll
        for (int d = 1; d < 32; d <<= 1) {
            int y = __shfl_up_sync(0xFFFFFFFFu, s, d);
            if (tid >= d) s += y;
        }
        wsum[tid] = s;
    }
    __syncthreads();
    int incl = x + (wid ? wsum[wid - 1] : 0) + sbase;
    if (i < NN) {
        int excl = incl - v;
        g_offsets[i] = excl;
        g_cursor[i]  = excl;
        g_counts[i]  = 0;            // leave zero for the next invocation
    }
    if (j == 0 && tid == 0) g_offsets[NN] = EE;
}

// ---------------- CSR scatter (after scanB) ----------------------------------
__global__ __launch_bounds__(256) void scatter_kernel(const int*   __restrict__ rows,
                                                      const int*   __restrict__ cols,
                                                      const float* __restrict__ vals) {
    int i = blockIdx.x * 256 + threadIdx.x;
    if (i < EE / 4) {
        int4   r4 = ((const int4*)rows)[i];
        int4   c4 = ((const int4*)cols)[i];
        float4 v4 = ((const float4*)vals)[i];
        int p;
        p = atomicAdd(&g_cursor[r4.x], 1);
        g_csr[p] = make_int2(c4.x, __float_as_int(v4.x));
        p = atomicAdd(&g_cursor[r4.y], 1);
        g_csr[p] = make_int2(c4.y, __float_as_int(v4.y));
        p = atomicAdd(&g_cursor[r4.z], 1);
        g_csr[p] = make_int2(c4.z, __float_as_int(v4.z));
        p = atomicAdd(&g_cursor[r4.w], 1);
        g_csr[p] = make_int2(c4.w, __float_as_int(v4.w));
    }
}

// ---------------- fused: histogram + HMMA projection -------------------------
// proj tile: 32 nodes x 4 batches (128 A-rows) x 64 outs; 256 threads, 8 warps.
// Epilogue staged through smem for coalesced global writes.
#define XS_STRIDE 72    // halves; frag LDS bank = 4g+tig, conflict-free
#define SL_STRIDE 132   // halves per node in slin (264B, 8B-aligned rows)
#define SE_STRIDE 34    // floats per row in seye (136B, 8B-aligned rows)
#define SMEM_BYTES 28672
__global__ __launch_bounds__(256, 3) void fused_hist_proj_kernel(
    const int*   __restrict__ rows,
    const float* __restrict__ x,
    const float* __restrict__ Wlin,
    const float* __restrict__ Weye,
    const float* __restrict__ beye,
    float*       __restrict__ out)
{
    __shared__ __align__(16) char sm[SMEM_BYTES];

    const int tid = threadIdx.x;

    if (blockIdx.x < SCAT_BLOCKS) {
        // ---- histogram: 4 edges / thread via int4 ----
        int i = blockIdx.x * 256 + tid;
        if (i < EE / 4) {
            int4 r = ((const int4*)rows)[i];
            atomicAdd(&g_counts[r.x], 1);
            atomicAdd(&g_counts[r.y], 1);
            atomicAdd(&g_counts[r.z], 1);
            atomicAdd(&g_counts[r.w], 1);
        }
        return;
    }

    // ---- projection ----
    __half* xs = (__half*)sm;                       // [128][XS_STRIDE]
    __half* wt = (__half*)(sm + 128 * XS_STRIDE * 2);  // [64][XS_STRIDE]

    const int node0 = (blockIdx.x - SCAT_BLOCKS) * 32;

    // Stage x (128 rows = 4b x 32 nodes, 64 ch) + W^T (64 n x 64 k) as fp16.
    #pragma unroll
    for (int it = 0; it < 12; ++it) {
        int idx = tid + it * 256;                   // 0..3071
        if (idx < 2048) {
            int row = idx >> 4;                     // 0..127
            int c4  = (idx & 15) << 2;
            int b   = row >> 5;
            int node = row & 31;
            int nn  = node0 + node; if (nn >= NN) nn = NN - 1;
            float4 v = *(const float4*)(x + ((size_t)(b * NN + nn)) * 64 + c4);
            *(__half2*)&xs[row * XS_STRIDE + c4]     = __floats2half2_rn(v.x, v.y);
            *(__half2*)&xs[row * XS_STRIDE + c4 + 2] = __floats2half2_rn(v.z, v.w);
        } else {
            int id2 = idx - 2048;                   // 0..1023
            int row = id2 >> 4;                     // 0..63
            int c4  = (id2 & 15) << 2;
            const float* wsrc = (row < 32) ? (Wlin + row * 64 + c4)
                                           : (Weye + (row - 32) * 64 + c4);
            float4 w = *(const float4*)wsrc;
            *(__half2*)&wt[row * XS_STRIDE + c4]     = __floats2half2_rn(w.x, w.y);
            *(__half2*)&wt[row * XS_STRIDE + c4 + 2] = __floats2half2_rn(w.z, w.w);
        }
    }
    __syncthreads();

    const int warp = tid >> 5;
    const int lane = tid & 31;
    const int g    = lane >> 2;        // 0..7
    const int tig  = lane & 3;         // 0..3
    const int wrow = warp * 16;        // warp's A-row base

    float d[8][4];
    #pragma unroll
    for (int nf = 0; nf < 8; ++nf)
        #pragma unroll
        for (int k = 0; k < 4; ++k) d[nf][k] = 0.f;

    #pragma unroll
    for (int kc = 0; kc < 4; ++kc) {
        const int kb = kc * 16;
        unsigned a0 = *(const unsigned*)&xs[(wrow + g)     * XS_STRIDE + kb + 2 * tig];
        unsigned a1 = *(const unsigned*)&xs[(wrow + g + 8) * XS_STRIDE + kb + 2 * tig];
        unsigned a2 = *(const unsigned*)&xs[(wrow + g)     * XS_STRIDE + kb + 2 * tig + 8];
        unsigned a3 = *(const unsigned*)&xs[(wrow + g + 8) * XS_STRIDE + kb + 2 * tig + 8];
        #pragma unroll
        for (int nf = 0; nf < 8; ++nf) {
            unsigned b0 = *(const unsigned*)&wt[(nf * 8 + g) * XS_STRIDE + kb + 2 * tig];
            unsigned b1 = *(const unsigned*)&wt[(nf * 8 + g) * XS_STRIDE + kb + 2 * tig + 8];
            mma16816(d[nf][0], d[nf][1], d[nf][2], d[nf][3],
                     a0, a1, a2, a3, b0, b1);
        }
    }

    // biases for eye columns (2 per frag)
    float be[4][2];
    #pragma unroll
    for (int nf = 4; nf < 8; ++nf) {
        int oc = nf * 8 + 2 * tig - 32;
        be[nf - 4][0] = __ldg(&beye[oc]);
        be[nf - 4][1] = __ldg(&beye[oc + 1]);
    }

    __syncthreads();   // done reading xs/wt; reuse smem for output staging

    __half* slin = (__half*)sm;                        // [32][SL_STRIDE] halves
    float*  seye = (float*)(sm + 32 * SL_STRIDE * 2);  // [128][SE_STRIDE] floats

    const int b        = warp >> 1;            // batch this warp owns
    const int nodeBase = (warp & 1) * 16;

    #pragma unroll
    for (int h2 = 0; h2 < 2; ++h2) {
        int node = nodeBase + g + 8 * h2;
        int r    = wrow + g + 8 * h2;          // tile row = 32*b + node
        // lin frags -> slin[node][ch*4 + b]
        #pragma unroll
        for (int nf = 0; nf < 4; ++nf) {
            int ch = nf * 8 + 2 * tig;
            float v0 = h2 ? d[nf][2] : d[nf][0];
            float v1 = h2 ? d[nf][3] : d[nf][1];
            slin[node * SL_STRIDE + ch * 4 + b]       = __float2half_rn(v0);
            slin[node * SL_STRIDE + (ch + 1) * 4 + b] = __float2half_rn(v1);
        }
        // eye frags + bias -> seye[r][c]
        #pragma unroll
        for (int nf = 4; nf < 8; ++nf) {
            int c = (nf - 4) * 8 + 2 * tig;
            float v0 = (h2 ? d[nf][2] : d[nf][0]) + be[nf - 4][0];
            float v1 = (h2 ? d[nf][3] : d[nf][1]) + be[nf - 4][1];
            seye[r * SE_STRIDE + c]     = v0;
            seye[r * SE_STRIDE + c + 1] = v1;
        }
    }
    __syncthreads();

    // cooperative coalesced writes
    // slin -> g_hlin : 32 nodes x 32 uint2 (4 halves each)
    #pragma unroll
    for (int it = 0; it < 4; ++it) {
        int idx  = tid + it * 256;             // 0..1023
        int node = idx >> 5;
        int q    = idx & 31;
        int n    = node0 + node;
        if (n < NN) {
            uint2 v = *(const uint2*)&slin[node * SL_STRIDE + q * 4];
            *(uint2*)&g_hlin[(size_t)n * 128 + q * 4] = v;
        }
    }
    // seye -> out upper half : 128 rows x 16 float2
    #pragma unroll
    for (int it = 0; it < 8; ++it) {
        int idx = tid + it * 256;              // 0..2047
        int row = idx >> 4;
        int q   = idx & 15;
        int bb  = row >> 5;
        int node = row & 31;
        int n   = node0 + node;
        if (n < NN) {
            float2 v = *(const float2*)&seye[row * SE_STRIDE + q * 2];
            *(float2*)&out[((size_t)bb * NN + n) * 64 + 32 + q * 2] = v;
        }
    }
}

// ---------------- gather: one warp per node, all 4 batches, fp16 h ----------
__global__ __launch_bounds__(256) void gather_kernel(const float* __restrict__ blin,
                                                     float* __restrict__ out) {
    int n    = (blockIdx.x * blockDim.x + threadIdx.x) >> 5;
    int lane = threadIdx.x & 31;
    if (n >= NN) return;

    int s = g_offsets[n];
    int t = g_offsets[n + 1];

    float a0 = 0.f, a1 = 0.f, a2 = 0.f, a3 = 0.f;
    int e = s;
    for (; e + 4 <= t; e += 4) {
        int2 p0 = g_csr[e];
        int2 p1 = g_csr[e + 1];
        int2 p2 = g_csr[e + 2];
        int2 p3 = g_csr[e + 3];
        uint2 q0 = *(const uint2*)(g_hlin + (size_t)p0.x * 128 + lane * 4);
        uint2 q1 = *(const uint2*)(g_hlin + (size_t)p1.x * 128 + lane * 4);
        uint2 q2 = *(const uint2*)(g_hlin + (size_t)p2.x * 128 + lane * 4);
        uint2 q3 = *(const uint2*)(g_hlin + (size_t)p3.x * 128 + lane * 4);
        float s0 = __int_as_float(p0.y), s1 = __int_as_float(p1.y);
        float s2 = __int_as_float(p2.y), s3 = __int_as_float(p3.y);
        float2 u01, u23;
        u01 = __half22float2(*(__half2*)&q0.x); u23 = __half22float2(*(__half2*)&q0.y);
        a0 += s0 * u01.x; a1 += s0 * u01.y; a2 += s0 * u23.x; a3 += s0 * u23.y;
        u01 = __half22float2(*(__half2*)&q1.x); u23 = __half22float2(*(__half2*)&q1.y);
        a0 += s1 * u01.x; a1 += s1 * u01.y; a2 += s1 * u23.x; a3 += s1 * u23.y;
        u01 = __half22float2(*(__half2*)&q2.x); u23 = __half22float2(*(__half2*)&q2.y);
        a0 += s2 * u01.x; a1 += s2 * u01.y; a2 += s2 * u23.x; a3 += s2 * u23.y;
        u01 = __half22float2(*(__half2*)&q3.x); u23 = __half22float2(*(__half2*)&q3.y);
        a0 += s3 * u01.x; a1 += s3 * u01.y; a2 += s3 * u23.x; a3 += s3 * u23.y;
    }
    for (; e < t; ++e) {
        int2 p = g_csr[e];
        uint2 q = *(const uint2*)(g_hlin + (size_t)p.x * 128 + lane * 4);
        float sv = __int_as_float(p.y);
        float2 u01 = __half22float2(*(__half2*)&q.x);
        float2 u23 = __half22float2(*(__half2*)&q.y);
        a0 += sv * u01.x; a1 += sv * u01.y; a2 += sv * u23.x; a3 += sv * u23.y;
    }

    float bl = blin[lane];
    out[((size_t)0 * NN + n) * 64 + lane] = a0 + bl;
    out[((size_t)1 * NN + n) * 64 + lane] = a1 + bl;
    out[((size_t)2 * NN + n) * 64 + lane] = a2 + bl;
    out[((size_t)3 * NN + n) * 64 + lane] = a3 + bl;
}

// ---------------- launch -----------------------------------------------------
extern "C" void kernel_launch(void* const* d_in, const int* in_sizes, int n_in,
                              void* d_out, int out_size) {
    const float* x    = (const float*)d_in[0];
    const float* vals = (const float*)d_in[1];
    const float* Wlin = (const float*)d_in[2];
    const float* blin = (const float*)d_in[3];
    const float* Weye = (const float*)d_in[4];
    const float* beye = (const float*)d_in[5];
    const int*   rows = (const int*)d_in[6];
    const int*   cols = (const int*)d_in[7];
    float* out = (float*)d_out;
    (void)in_sizes; (void)n_in; (void)out_size;

    // g_counts is zero on entry (zero-init at load; scanB re-zeros each call)
    fused_hist_proj_kernel<<<SCAT_BLOCKS + PROJ_BLOCKS, 256>>>(
        rows, x, Wlin, Weye, beye, out);
    scanA_kernel<<<SCANB_BLOCKS, 1024>>>();
    scanB_kernel<<<SCANB_BLOCKS, 1024>>>();
    scatter_kernel<<<SCAT_BLOCKS, 256>>>(rows, cols, vals);
    gather_kernel<<<(NN * 32 + 255) / 256, 256>>>(blin, out);
}

// round 8
// speedup vs baseline: 1.9050x; 1.0301x over previous
#include <cuda_runtime.h>
#include <cuda_fp16.h>
#include <cstdint>

// Problem constants (fixed shapes for this dataset)
#define BB   4
#define NN   50000
#define CIN  64
#define EE   800000
#define HALF 32
#define BN   (BB * NN)           // 200000

#define HIST_BLOCKS  782         // ceil(EE/4 / 256), 4 edges/thread
#define SCAT_BLOCKS  1563        // ceil(EE/2 / 256), 2 edges/thread
#define PROJ_BLOCKS  1563        // ceil(NN / 32)
#define PROJ_A       940         // proj blocks in K1 (with hist)
#define PROJ_B       623         // proj blocks in K2 (with scatter)
#define SCANB_BLOCKS 49          // ceil(NN/1024)

// ---------------- scratch (device globals; zero-initialized at load) --------
__device__ __half g_hlin[NN * 128];    // [n][ch][b]  half, 12.8 MB (L2-resident)
__device__ int    g_counts[NN];        // kept zero between calls (scanB re-zeros)
__device__ int    g_offsets[NN + 1];
__device__ int    g_cursor[NN];
__device__ int2   g_csr[EE];           // .x = col, .y = bits(val)
__device__ int    g_blocksums[64];

// ---------------- mma helper -------------------------------------------------
__device__ __forceinline__ void mma16816(float& d0, float& d1, float& d2, float& d3,
                                         unsigned a0, unsigned a1, unsigned a2, unsigned a3,
                                         unsigned b0, unsigned b1) {
    asm("mma.sync.aligned.m16n8k16.row.col.f32.f16.f16.f32 "
        "{%0,%1,%2,%3}, {%4,%5,%6,%7}, {%8,%9}, {%0,%1,%2,%3};"
        : "+f"(d0), "+f"(d1), "+f"(d2), "+f"(d3)
        : "r"(a0), "r"(a1), "r"(a2), "r"(a3), "r"(b0), "r"(b1));
}

// ---------------- shared projection body -------------------------------------
// tile: 32 nodes x 4 batches (128 A-rows) x 64 outs; 256 threads, 8 warps.
#define XS_STRIDE 72    // halves; frag LDS bank = 4g+tig, conflict-free
#define SL_STRIDE 132   // halves per node in slin
#define SE_STRIDE 34    // floats per row in seye
#define SMEM_BYTES 28672

__device__ __forceinline__ void proj_tile(
    char* sm, int node0, int tid,
    const float* __restrict__ x,
    const float* __restrict__ Wlin,
    const float* __restrict__ Weye,
    const float* __restrict__ beye,
    float*       __restrict__ out)
{
    __half* xs = (__half*)sm;                          // [128][XS_STRIDE]
    __half* wt = (__half*)(sm + 128 * XS_STRIDE * 2);  // [64][XS_STRIDE]

    // Stage x (128 rows = 4b x 32 nodes, 64 ch) + W^T (64 n x 64 k) as fp16.
    #pragma unroll
    for (int it = 0; it < 12; ++it) {
        int idx = tid + it * 256;                   // 0..3071
        if (idx < 2048) {
            int row = idx >> 4;                     // 0..127
            int c4  = (idx & 15) << 2;
            int b   = row >> 5;
            int node = row & 31;
            int nn  = node0 + node; if (nn >= NN) nn = NN - 1;
            float4 v = *(const float4*)(x + ((size_t)(b * NN + nn)) * 64 + c4);
            *(__half2*)&xs[row * XS_STRIDE + c4]     = __floats2half2_rn(v.x, v.y);
            *(__half2*)&xs[row * XS_STRIDE + c4 + 2] = __floats2half2_rn(v.z, v.w);
        } else {
            int id2 = idx - 2048;                   // 0..1023
            int row = id2 >> 4;                     // 0..63
            int c4  = (id2 & 15) << 2;
            const float* wsrc = (row < 32) ? (Wlin + row * 64 + c4)
                                           : (Weye + (row - 32) * 64 + c4);
            float4 w = *(const float4*)wsrc;
            *(__half2*)&wt[row * XS_STRIDE + c4]     = __floats2half2_rn(w.x, w.y);
            *(__half2*)&wt[row * XS_STRIDE + c4 + 2] = __floats2half2_rn(w.z, w.w);
        }
    }
    __syncthreads();

    const int warp = tid >> 5;
    const int lane = tid & 31;
    const int g    = lane >> 2;        // 0..7
    const int tig  = lane & 3;         // 0..3
    const int wrow = warp * 16;        // warp's A-row base

    float d[8][4];
    #pragma unroll
    for (int nf = 0; nf < 8; ++nf)
        #pragma unroll
        for (int k = 0; k < 4; ++k) d[nf][k] = 0.f;

    #pragma unroll
    for (int kc = 0; kc < 4; ++kc) {
        const int kb = kc * 16;
        unsigned a0 = *(const unsigned*)&xs[(wrow + g)     * XS_STRIDE + kb + 2 * tig];
        unsigned a1 = *(const unsigned*)&xs[(wrow + g + 8) * XS_STRIDE + kb + 2 * tig];
        unsigned a2 = *(const unsigned*)&xs[(wrow + g)     * XS_STRIDE + kb + 2 * tig + 8];
        unsigned a3 = *(const unsigned*)&xs[(wrow + g + 8) * XS_STRIDE + kb + 2 * tig + 8];
        #pragma unroll
        for (int nf = 0; nf < 8; ++nf) {
            unsigned b0 = *(const unsigned*)&wt[(nf * 8 + g) * XS_STRIDE + kb + 2 * tig];
            unsigned b1 = *(const unsigned*)&wt[(nf * 8 + g) * XS_STRIDE + kb + 2 * tig + 8];
            mma16816(d[nf][0], d[nf][1], d[nf][2], d[nf][3],
                     a0, a1, a2, a3, b0, b1);
        }
    }

    // biases for eye columns (2 per frag)
    float be[4][2];
    #pragma unroll
    for (int nf = 4; nf < 8; ++nf) {
        int oc = nf * 8 + 2 * tig - 32;
        be[nf - 4][0] = __ldg(&beye[oc]);
        be[nf - 4][1] = __ldg(&beye[oc + 1]);
    }

    __syncthreads();   // done reading xs/wt; reuse smem for output staging

    __half* slin = (__half*)sm;                        // [32][SL_STRIDE] halves
    float*  seye = (float*)(sm + 32 * SL_STRIDE * 2);  // [128][SE_STRIDE] floats

    const int b        = warp >> 1;            // batch this warp owns
    const int nodeBase = (warp & 1) * 16;

    #pragma unroll
    for (int h2 = 0; h2 < 2; ++h2) {
        int node = nodeBase + g + 8 * h2;
        int r    = wrow + g + 8 * h2;          // tile row = 32*b + node
        #pragma unroll
        for (int nf = 0; nf < 4; ++nf) {
            int ch = nf * 8 + 2 * tig;
            float v0 = h2 ? d[nf][2] : d[nf][0];
            float v1 = h2 ? d[nf][3] : d[nf][1];
            slin[node * SL_STRIDE + ch * 4 + b]       = __float2half_rn(v0);
            slin[node * SL_STRIDE + (ch + 1) * 4 + b] = __float2half_rn(v1);
        }
        #pragma unroll
        for (int nf = 4; nf < 8; ++nf) {
            int c = (nf - 4) * 8 + 2 * tig;
            float v0 = (h2 ? d[nf][2] : d[nf][0]) + be[nf - 4][0];
            float v1 = (h2 ? d[nf][3] : d[nf][1]) + be[nf - 4][1];
            seye[r * SE_STRIDE + c]     = v0;
            seye[r * SE_STRIDE + c + 1] = v1;
        }
    }
    __syncthreads();

    // cooperative coalesced writes
    #pragma unroll
    for (int it = 0; it < 4; ++it) {
        int idx  = tid + it * 256;             // 0..1023
        int node = idx >> 5;
        int q    = idx & 31;
        int n    = node0 + node;
        if (n < NN) {
            uint2 v = *(const uint2*)&slin[node * SL_STRIDE + q * 4];
            *(uint2*)&g_hlin[(size_t)n * 128 + q * 4] = v;
        }
    }
    #pragma unroll
    for (int it = 0; it < 8; ++it) {
        int idx = tid + it * 256;              // 0..2047
        int row = idx >> 4;
        int q   = idx & 15;
        int bb  = row >> 5;
        int node = row & 31;
        int n   = node0 + node;
        if (n < NN) {
            float2 v = *(const float2*)&seye[row * SE_STRIDE + q * 2];
            *(float2*)&out[((size_t)bb * NN + n) * 64 + 32 + q * 2] = v;
        }
    }
}

// ---------------- K1: projA (blocks first) + histogram -----------------------
__global__ __launch_bounds__(256, 3) void k1_proj_hist_kernel(
    const int*   __restrict__ rows,
    const float* __restrict__ x,
    const float* __restrict__ Wlin,
    const float* __restrict__ Weye,
    const float* __restrict__ beye,
    float*       __restrict__ out)
{
    __shared__ __align__(16) char sm[SMEM_BYTES];
    const int tid = threadIdx.x;

    if (blockIdx.x < PROJ_A) {
        proj_tile(sm, blockIdx.x * 32, tid, x, Wlin, Weye, beye, out);
        return;
    }
    // ---- histogram: 4 edges / thread via int4 ----
    int i = (blockIdx.x - PROJ_A) * 256 + tid;
    if (i < EE / 4) {
        int4 r = ((const int4*)rows)[i];
        atomicAdd(&g_counts[r.x], 1);
        atomicAdd(&g_counts[r.y], 1);
        atomicAdd(&g_counts[r.z], 1);
        atomicAdd(&g_counts[r.w], 1);
    }
}

// ---------------- scan phase A: per-1024-chunk sums --------------------------
__global__ __launch_bounds__(1024) void scanA_kernel() {
    __shared__ int ws[32];
    const int tid = threadIdx.x, lane = tid & 31, wid = tid >> 5;
    int i = blockIdx.x * 1024 + tid;
    int v = (i < NN) ? g_counts[i] : 0;
    #pragma unroll
    for (int d = 16; d > 0; d >>= 1) v += __shfl_down_sync(0xFFFFFFFFu, v, d);
    if (lane == 0) ws[wid] = v;
    __syncthreads();
    if (tid < 32) {
        int s = ws[tid];
        #pragma unroll
        for (int d = 16; d > 0; d >>= 1) s += __shfl_down_sync(0xFFFFFFFFu, s, d);
        if (tid == 0) g_blocksums[blockIdx.x] = s;
    }
}

// ---------------- scan phase B: local scan + parallel base; re-zero counts ---
__global__ __launch_bounds__(1024) void scanB_kernel() {
    __shared__ int wsum[32];
    __shared__ int sbase;
    const int tid = threadIdx.x, lane = tid & 31, wid = tid >> 5;
    const int j = blockIdx.x;

    if (wid == 0) {
        int v = 0;
        for (int k = lane; k < j; k += 32) v += g_blocksums[k];
        #pragma unroll
        for (int d = 16; d > 0; d >>= 1) v += __shfl_down_sync(0xFFFFFFFFu, v, d);
        if (lane == 0) sbase = v;
    }

    int i = j * 1024 + tid;
    int v = (i < NN) ? g_counts[i] : 0;
    int x = v;
    #pragma unroll
    for (int d = 1; d < 32; d <<= 1) {
        int y = __shfl_up_sync(0xFFFFFFFFu, x, d);
        if (lane >= d) x += y;
    }
    if (lane == 31) wsum[wid] = x;
    __syncthreads();
    if (tid < 32) {
        int s = wsum[tid];
        #pragma unroll
        for (int d = 1; d < 32; d <<= 1) {
            int y = __shfl_up_sync(0xFFFFFFFFu, s, d);
            if (tid >= d) s += y;
        }
        wsum[tid] = s;
    }
    __syncthreads();
    int incl = x + (wid ? wsum[wid - 1] : 0) + sbase;
    if (i < NN) {
        int excl = incl - v;
        g_offsets[i] = excl;
        g_cursor[i]  = excl;
        g_counts[i]  = 0;            // leave zero for the next invocation
    }
    if (j == 0 && tid == 0) g_offsets[NN] = EE;
}

// ---------------- K2: projB (blocks first) + CSR scatter ---------------------
__global__ __launch_bounds__(256, 3) void k2_proj_scatter_kernel(
    const int*   __restrict__ rows,
    const int*   __restrict__ cols,
    const float* __restrict__ vals,
    const float* __restrict__ x,
    const float* __restrict__ Wlin,
    const float* __restrict__ Weye,
    const float* __restrict__ beye,
    float*       __restrict__ out)
{
    __shared__ __align__(16) char sm[SMEM_BYTES];
    const int tid = threadIdx.x;

    if (blockIdx.x < PROJ_B) {
        proj_tile(sm, (PROJ_A + blockIdx.x) * 32, tid, x, Wlin, Weye, beye, out);
        return;
    }
    // ---- scatter: 2 edges / thread via int2/float2 ----
    int i = (blockIdx.x - PROJ_B) * 256 + tid;
    if (i < EE / 2) {
        int2   r2 = ((const int2*)rows)[i];
        int2   c2 = ((const int2*)cols)[i];
        float2 v2 = ((const float2*)vals)[i];
        int p;
        p = atomicAdd(&g_cursor[r2.x], 1);
        g_csr[p] = make_int2(c2.x, __float_as_int(v2.x));
        p = atomicAdd(&g_cursor[r2.y], 1);
        g_csr[p] = make_int2(c2.y, __float_as_int(v2.y));
    }
}

// ---------------- gather: one warp per node, all 4 batches, fp16 h ----------
__global__ __launch_bounds__(256) void gather_kernel(const float* __restrict__ blin,
                                                     float* __restrict__ out) {
    int n    = (blockIdx.x * blockDim.x + threadIdx.x) >> 5;
    int lane = threadIdx.x & 31;
    if (n >= NN) return;

    int s = g_offsets[n];
    int t = g_offsets[n + 1];

    float a0 = 0.f, a1 = 0.f, a2 = 0.f, a3 = 0.f;
    int e = s;
    for (; e + 4 <= t; e += 4) {
        int2 p0 = g_csr[e];
        int2 p1 = g_csr[e + 1];
        int2 p2 = g_csr[e + 2];
        int2 p3 = g_csr[e + 3];
        uint2 q0 = *(const uint2*)(g_hlin + (size_t)p0.x * 128 + lane * 4);
        uint2 q1 = *(const uint2*)(g_hlin + (size_t)p1.x * 128 + lane * 4);
        uint2 q2 = *(const uint2*)(g_hlin + (size_t)p2.x * 128 + lane * 4);
        uint2 q3 = *(const uint2*)(g_hlin + (size_t)p3.x * 128 + lane * 4);
        float s0 = __int_as_float(p0.y), s1 = __int_as_float(p1.y);
        float s2 = __int_as_float(p2.y), s3 = __int_as_float(p3.y);
        float2 u01, u23;
        u01 = __half22float2(*(__half2*)&q0.x); u23 = __half22float2(*(__half2*)&q0.y);
        a0 += s0 * u01.x; a1 += s0 * u01.y; a2 += s0 * u23.x; a3 += s0 * u23.y;
        u01 = __half22float2(*(__half2*)&q1.x); u23 = __half22float2(*(__half2*)&q1.y);
        a0 += s1 * u01.x; a1 += s1 * u01.y; a2 += s1 * u23.x; a3 += s1 * u23.y;
        u01 = __half22float2(*(__half2*)&q2.x); u23 = __half22float2(*(__half2*)&q2.y);
        a0 += s2 * u01.x; a1 += s2 * u01.y; a2 += s2 * u23.x; a3 += s2 * u23.y;
        u01 = __half22float2(*(__half2*)&q3.x); u23 = __half22float2(*(__half2*)&q3.y);
        a0 += s3 * u01.x; a1 += s3 * u01.y; a2 += s3 * u23.x; a3 += s3 * u23.y;
    }
    for (; e < t; ++e) {
        int2 p = g_csr[e];
        uint2 q = *(const uint2*)(g_hlin + (size_t)p.x * 128 + lane * 4);
        float sv = __int_as_float(p.y);
        float2 u01 = __half22float2(*(__half2*)&q.x);
        float2 u23 = __half22float2(*(__half2*)&q.y);
        a0 += sv * u01.x; a1 += sv * u01.y; a2 += sv * u23.x; a3 += sv * u23.y;
    }

    float bl = blin[lane];
    out[((size_t)0 * NN + n) * 64 + lane] = a0 + bl;
    out[((size_t)1 * NN + n) * 64 + lane] = a1 + bl;
    out[((size_t)2 * NN + n) * 64 + lane] = a2 + bl;
    out[((size_t)3 * NN + n) * 64 + lane] = a3 + bl;
}

// ---------------- launch -----------------------------------------------------
extern "C" void kernel_launch(void* const* d_in, const int* in_sizes, int n_in,
                              void* d_out, int out_size) {
    const float* x    = (const float*)d_in[0];
    const float* vals = (const float*)d_in[1];
    const float* Wlin = (const float*)d_in[2];
    const float* blin = (const float*)d_in[3];
    const float* Weye = (const float*)d_in[4];
    const float* beye = (const float*)d_in[5];
    const int*   rows = (const int*)d_in[6];
    const int*   cols = (const int*)d_in[7];
    float* out = (float*)d_out;
    (void)in_sizes; (void)n_in; (void)out_size;

    // g_counts is zero on entry (zero-init at load; scanB re-zeros each call)
    k1_proj_hist_kernel<<<PROJ_A + HIST_BLOCKS, 256>>>(
        rows, x, Wlin, Weye, beye, out);
    scanA_kernel<<<SCANB_BLOCKS, 1024>>>();
    scanB_kernel<<<SCANB_BLOCKS, 1024>>>();
    k2_proj_scatter_kernel<<<PROJ_B + SCAT_BLOCKS, 256>>>(
        rows, cols, vals, x, Wlin, Weye, beye, out);
    gather_kernel<<<(NN * 32 + 255) / 256, 256>>>(blin, out);
}